// round 17
// baseline (speedup 1.0000x reference)
#include <cuda_runtime.h>
#include <cuda_bf16.h>

#define MAX_SEG 16384
#define PAD 32   // one float counter per 128B L2 line

// Padded scatter accumulators: track/hit separated, one counter per 128B
// line. Zero-initialized at module load; the fused corr phase self-cleans
// after reading, so every launch starts from a clean state.
__device__ float g_track[MAX_SEG * PAD];
__device__ float g_hit[MAX_SEG * PAD];

// Packed table for the gather phase: ONE 16B read per hit (L1-resident).
//   x = e_track_raw  y = e_track_corr  z = e_hit_raw  w = e_hit_corr
__device__ float4 g_shower[MAX_SEG];

// Device-wide barrier state for the fused corr+gather kernel.
// Reset to 0 by the last departing CTA -> clean state for every graph replay.
__device__ unsigned g_arrive = 0;
__device__ unsigned g_depart = 0;

__device__ __forceinline__ void stcs_f4(float4* p, float4 v) {
    asm volatile("st.global.cs.v4.f32 [%0], {%1,%2,%3,%4};"
                 :: "l"(p), "f"(v.x), "f"(v.y), "f"(v.z), "f"(v.w)
                 : "memory");
}
// Evict-last 32B load (8 x b32): keep sid in L2 for the downstream gather.
__device__ __forceinline__ void ldel_v8(const int* p, int* s) {
    asm volatile(
        "ld.global.L2::evict_last.v8.b32 {%0,%1,%2,%3,%4,%5,%6,%7}, [%8];"
        : "=r"(s[0]), "=r"(s[1]), "=r"(s[2]), "=r"(s[3]),
          "=r"(s[4]), "=r"(s[5]), "=r"(s[6]), "=r"(s[7])
        : "l"(p));
}
// Evict-first: single-use streams.
__device__ __forceinline__ int4 ldcs_i4(const int4* p) {
    int4 v;
    asm volatile("ld.global.cs.v4.s32 {%0,%1,%2,%3}, [%4];"
                 : "=r"(v.x), "=r"(v.y), "=r"(v.z), "=r"(v.w) : "l"(p));
    return v;
}
__device__ __forceinline__ float4 ldcs_f4(const float4* p) {
    float4 v;
    asm volatile("ld.global.cs.v4.f32 {%0,%1,%2,%3}, [%4];"
                 : "=f"(v.x), "=f"(v.y), "=f"(v.z), "=f"(v.w) : "l"(p));
    return v;
}
__device__ __forceinline__ unsigned ld_acq(const unsigned* p) {
    unsigned v;
    asm volatile("ld.global.acquire.gpu.u32 %0, [%1];" : "=r"(v) : "l"(p));
    return v;
}

// ---------------------------------------------------------------------------
// Kernel 1: scatter — grid-stride one wave, 8 hits/iter. sid via one 32B
// evict_last load (reused by gather), energy/rid evict-first, then 8
// predicated global REDs. At the REDG wavefront-replay floor (~29us stable).
// Noise hits (sid == -1) contribute exactly 0 -> skipped.
// recHitID==1 -> track, ==0 -> hit.
// ---------------------------------------------------------------------------
__global__ void __launch_bounds__(256, 8) scatter8_gs_kernel(
        const int* __restrict__ sid,
        const float* __restrict__ energy,
        const int* __restrict__ rid,
        int ngroups,           // n/8 groups of 8 hits
        int n) {
    int stride = gridDim.x * blockDim.x;
    for (int t = blockIdx.x * blockDim.x + threadIdx.x; t < ngroups;
         t += stride) {
        int s[8];
        ldel_v8(sid + 8 * t, s);                       // 32B, 32B-aligned
        float4 e0 = ldcs_f4((const float4*)(energy) + 2*t);
        float4 e1 = ldcs_f4((const float4*)(energy) + 2*t + 1);
        int4   r0 = ldcs_i4((const int4*)(rid)      + 2*t);
        int4   r1 = ldcs_i4((const int4*)(rid)      + 2*t + 1);
        float e[8] = {e0.x, e0.y, e0.z, e0.w, e1.x, e1.y, e1.z, e1.w};
        int   r[8] = {r0.x, r0.y, r0.z, r0.w, r1.x, r1.y, r1.z, r1.w};
#pragma unroll
        for (int k = 0; k < 8; k++) {
            if (s[k] >= 0) {
                float* p = (r[k] == 1) ? &g_track[(s[k] + 1) * PAD]
                                       : &g_hit[(s[k] + 1) * PAD];
                atomicAdd(p, e[k]);
            }
        }
    }
    // Tail (n % 8 hits): one thread, <= 7 ops.
    if (blockIdx.x == 0 && threadIdx.x == 0) {
        for (int i = ngroups * 8; i < n; i++) {
            int sv = sid[i];
            if (sv >= 0) {
                float* p = (rid[i] == 1) ? &g_track[(sv + 1) * PAD]
                                         : &g_hit[(sv + 1) * PAD];
                atomicAdd(p, energy[i]);
            }
        }
    }
}

// ---------------------------------------------------------------------------
// Kernel 2: FUSED corr + gather. Launched as exactly ONE resident wave
// (grid <= 8 CTAs/SM x SMs, 0 smem, <=32 regs -> all CTAs co-resident, so the
// device-wide spin barrier cannot deadlock).
//
// Phase 1 (corr): thread g handles shower row g (nseg << total threads):
//   corr[s>=1] = pcf_ext[alpha_idx[s-1]]; pcf_ext[j] = pcf[j] if j < n_hits
//   and sid[j] != -1 else 0; corr[0] = 0. Repack into g_shower, self-clean
//   the accumulators. Then device-wide barrier (release arrive / acquire spin).
//
// Phase 2 (gather): grid-stride, 4 hits/iter (empirical optimum): 1 int4 sid
// load (L2-hit) -> 4 random 16B table reads -> 4 float4 STREAMING stores.
//   [0,n) e_track_raw [n,2n) e_track_corr [2n,3n) e_hit_raw [3n,4n) e_hit_corr
//
// Exit: departure counter; the LAST CTA resets both counters (clean replay).
// ---------------------------------------------------------------------------
__global__ void __launch_bounds__(256, 8) corr_gather_fused_kernel(
        const int* __restrict__ sid,
        const float* __restrict__ pcf,
        const int* __restrict__ a_tracks,
        const int* __restrict__ a_hits,
        float* __restrict__ out,
        int n_hits, int nseg, int nquads) {
    // ---- Phase 1: corr (one row per thread) ----
    int g = blockIdx.x * blockDim.x + threadIdx.x;
    if (g < nseg) {
        float ct = 0.f, ch = 0.f;
        if (g > 0) {
            int jt = a_tracks[g - 1];
            if (jt >= 0 && jt < n_hits && __ldg(sid + jt) != -1)
                ct = __ldg(pcf + jt);
            int jh = a_hits[g - 1];
            if (jh >= 0 && jh < n_hits && __ldg(sid + jh) != -1)
                ch = __ldg(pcf + jh);
        }
        float et = g_track[g * PAD];
        float eh = g_hit[g * PAD];
        g_shower[g] = make_float4(et, et * ct, eh, eh * ch);
        g_track[g * PAD] = 0.f;   // clean for the next launch
        g_hit[g * PAD]   = 0.f;
    }
    __threadfence();              // publish table writes
    __syncthreads();
    if (threadIdx.x == 0) {
        atomicAdd(&g_arrive, 1u);
        while (ld_acq(&g_arrive) < gridDim.x) { }
    }
    __syncthreads();

    // ---- Phase 2: gather ----
    int stride = gridDim.x * blockDim.x;
    int n = n_hits;
    for (int t = g; t < nquads; t += stride) {
        int4 s4 = __ldg((const int4*)(sid) + t);
        float4 v0 = g_shower[s4.x + 1];
        float4 v1 = g_shower[s4.y + 1];
        float4 v2 = g_shower[s4.z + 1];
        float4 v3 = g_shower[s4.w + 1];
        stcs_f4((float4*)(out)          + t, make_float4(v0.x, v1.x, v2.x, v3.x));
        stcs_f4((float4*)(out + n)      + t, make_float4(v0.y, v1.y, v2.y, v3.y));
        stcs_f4((float4*)(out + 2ll*n)  + t, make_float4(v0.z, v1.z, v2.z, v3.z));
        stcs_f4((float4*)(out + 3ll*n)  + t, make_float4(v0.w, v1.w, v2.w, v3.w));
    }
    // Tail (n % 4 hits): one thread.
    if (blockIdx.x == 0 && threadIdx.x == 0) {
        for (int i = nquads * 4; i < n; i++) {
            float4 v = g_shower[sid[i] + 1];
            out[i]          = v.x;
            out[i + 1ll*n]  = v.y;
            out[i + 2ll*n]  = v.z;
            out[i + 3ll*n]  = v.w;
        }
    }

    // ---- Exit: last CTA resets barrier state for the next graph replay ----
    __syncthreads();
    if (threadIdx.x == 0) {
        unsigned d = atomicAdd(&g_depart, 1u);
        if (d == gridDim.x - 1u) {
            g_arrive = 0u;
            g_depart = 0u;
            __threadfence();
        }
    }
}

extern "C" void kernel_launch(void* const* d_in, const int* in_sizes, int n_in,
                              void* d_out, int out_size) {
    const int*   pred_sid = (const int*)  d_in[0];
    const float* pcf      = (const float*)d_in[1];
    const float* energy   = (const float*)d_in[2];
    const int*   rid      = (const int*)  d_in[3];
    // d_in[4] = pred_beta (unused)
    const int*   a_tracks = (const int*)  d_in[5];
    const int*   a_hits   = (const int*)  d_in[6];
    float*       out      = (float*)d_out;

    int n_hits    = in_sizes[0];
    int n_showers = in_sizes[5];
    int nseg      = n_showers + 1;
    if (nseg > MAX_SEG) nseg = MAX_SEG;

    static int sm_count = 0;
    if (sm_count == 0) {
        cudaDeviceProp prop;
        cudaGetDeviceProperties(&prop, 0);
        sm_count = prop.multiProcessorCount;
        if (sm_count <= 0) sm_count = 148;
    }

    const int TPB = 256;
    long wave = 8L * sm_count;   // exactly one resident wave @ 8 CTAs/SM

    int ngroups = n_hits / 8;
    long sc_grid = ((long)ngroups + TPB - 1) / TPB;
    if (sc_grid > wave) sc_grid = wave;
    if (sc_grid < 1) sc_grid = 1;
    scatter8_gs_kernel<<<(unsigned)sc_grid, TPB>>>(pred_sid, energy, rid,
                                                   ngroups, n_hits);

    int nquads = n_hits / 4;
    long ga_grid = ((long)nquads + TPB - 1) / TPB;
    if (ga_grid > wave) ga_grid = wave;
    // The barrier requires enough threads to cover nseg in phase 1 AND all
    // CTAs resident; both hold (nseg <= grid*TPB since nseg <= 16384 and
    // grid*TPB >= 303K for this problem size; grid <= one wave).
    long min_grid = ((long)nseg + TPB - 1) / TPB;
    if (ga_grid < min_grid) ga_grid = min_grid;   // still << one wave
    if (ga_grid < 1) ga_grid = 1;
    corr_gather_fused_kernel<<<(unsigned)ga_grid, TPB>>>(
        pred_sid, pcf, a_tracks, a_hits, out, n_hits, nseg, nquads);
}